// round 13
// baseline (speedup 1.0000x reference)
#include <cuda_runtime.h>
#include <cuda_bf16.h>

// Constants exactly as the fp32 reference stores them (promoted via float).
// DT_Q = DT/4 and ADV4 = 4*ADVECT are EXACT binary rescalings that cancel the
// 4x-scaled gradient accumulator produced by the doubled-root NR.
#define DT_Q   ((double)0.2f  * 0.25)
#define ADV4   ((double)0.05f * 4.0)
#define EPS_C  ((double)1e-4f)

#define C0 ((double)-2.25f)
#define C1 ((double)-0.75f)
#define C2 ((double) 0.75f)
#define C3 ((double) 2.25f)
// Half-mus: exact binary halving of the promoted fp32 values.
#define MH0 ((double)0.5f * 0.5)
#define MH1 ((double)0.3f * 0.5)
#define MH2 ((double)0.6f * 0.5)
#define MH3 ((double)0.4f * 0.5)

// fp64 rsqrt seed: MUFU.RSQ64H (~2^-21 rel err).
__device__ __forceinline__ double rsq_seed(double x)
{
    double y;
    asm("rsqrt.approx.ftz.f64 %0, %1;" : "=d"(y) : "d"(x));
    return y;
}

// fp64 reciprocal: MUFU.RCP64H seed + 1 Newton -> ~1e-12 rel err.
__device__ __forceinline__ double drcp(double x)
{
    double y;
    asm("rcp.approx.ftz.f64 %0, %1;" : "=d"(y) : "d"(x));
    double t = __fma_rn(-x, y, 2.0);
    return y * t;
}

// Bit-exact clip to [-3, 3] on the ALU pipe (no fp64-pipe DSETP/SEL).
// IEEE-double total-order key: flip the 63 magnitude bits for negatives.
// key is an involution; integer min/max in key space == fp min/max for all
// non-NaN inputs (NaN impossible in this kernel). In-range values are
// returned bit-identically.
__device__ __forceinline__ double clip3(double x)
{
    long long b = __double_as_longlong(x);
    long long k = b ^ (long long)(((unsigned long long)(b >> 63)) >> 1);
    const long long K3  = 0x4008000000000000LL;               // key(+3.0)
    const long long Km3 = (long long)0xBFF7FFFFFFFFFFFFULL;   // key(-3.0)
    k = (k < K3)  ? k : K3;    // min in key space
    k = (k > Km3) ? k : Km3;   // max in key space
    long long r = k ^ (long long)(((unsigned long long)(k >> 63)) >> 1);
    return __longlong_as_double(r);
}

// One (j,k) interaction, doubled-root NR, r2 fused as fma(dx,dx,ey):
//   yc  = y0*(3 - r2*y0^2)  -> 2/r  (~1e-12)
//   w   = (mu/2)*yc         -> mu/r  (exact)
//   m3p = w*yc^2            -> 4*mu/r^3  (cancelled by DT_Q in epilogue)
// 10 fp64 slots + MUFU.
__device__ __forceinline__ void interact(double ey,
                                         double dx, double dy, double muh,
                                         double& nn, double& gx, double& gy)
{
    double r2  = __fma_rn(dx, dx, ey);
    double y0  = rsq_seed(r2);
    double t   = r2 * y0;
    double c   = __fma_rn(-t, y0, 3.0);
    double yc  = y0 * c;           // 2/r
    double w   = muh * yc;         // mu/r
    nn += w;
    double i2p = yc * yc;          // 4/r^2
    double m3p = w * i2p;          // 4*mu/r^3
    gx = __fma_rn(-m3p, dx, gx);
    gy = __fma_rn(-m3p, dy, gy);
}

__global__ __launch_bounds__(256)
void pmflow_kernel(const float2* __restrict__ z,
                   float2* __restrict__ out,
                   int n)
{
    int i = blockIdx.x * blockDim.x + threadIdx.x;
    if (i >= n) return;

    float2 zp = z[i];
    double zx = (double)zp.x;
    double zy = (double)zp.y;

#pragma unroll
    for (int s = 0; s < 6; s++) {
        // Separable per-axis precompute (scalar, no local arrays).
        double dx0 = zx - C0, dx1 = zx - C1, dx2_ = zx - C2, dx3 = zx - C3;
        double dy0 = zy - C0, dy1 = zy - C1, dy2_ = zy - C2, dy3 = zy - C3;

        double ey0 = __fma_rn(dy0, dy0, EPS_C);
        double ey1 = __fma_rn(dy1, dy1, EPS_C);
        double ey2 = __fma_rn(dy2_, dy2_, EPS_C);
        double ey3 = __fma_rn(dy3, dy3, EPS_C);

        // Two independent partial accumulator chains.
        double nnA = 1.0, gxA = 0.0, gyA = 0.0;   // chains for j=0,1
        double nnB = 0.0, gxB = 0.0, gyB = 0.0;   // chains for j=2,3

        interact(ey0, dx0, dy0, MH0, nnA, gxA, gyA);
        interact(ey0, dx2_, dy0, MH0, nnB, gxB, gyB);
        interact(ey1, dx0, dy1, MH1, nnA, gxA, gyA);
        interact(ey1, dx2_, dy1, MH1, nnB, gxB, gyB);
        interact(ey2, dx0, dy2_, MH2, nnA, gxA, gyA);
        interact(ey2, dx2_, dy2_, MH2, nnB, gxB, gyB);
        interact(ey3, dx0, dy3, MH3, nnA, gxA, gyA);
        interact(ey3, dx2_, dy3, MH3, nnB, gxB, gyB);

        interact(ey0, dx1, dy0, MH0, nnA, gxA, gyA);
        interact(ey0, dx3, dy0, MH0, nnB, gxB, gyB);
        interact(ey1, dx1, dy1, MH1, nnA, gxA, gyA);
        interact(ey1, dx3, dy1, MH1, nnB, gxB, gyB);
        interact(ey2, dx1, dy2_, MH2, nnA, gxA, gyA);
        interact(ey2, dx3, dy2_, MH2, nnB, gxB, gyB);
        interact(ey3, dx1, dy3, MH3, nnA, gxA, gyA);
        interact(ey3, dx3, dy3, MH3, nnB, gxB, gyB);

        double nn = nnA + nnB;
        double gx = gxA + gxB;     // = 4 * true gx
        double gy = gyA + gyB;     // = 4 * true gy

        double invn = drcp(nn);
        double gxi  = gx * invn;                // 4 * gx/n
        double a    = __fma_rn(gy, invn, ADV4); // 4 * (gy/n + ADVECT)
        zx = __fma_rn(DT_Q, gxi, zx);           // DT/4 cancels the 4 exactly
        zy = __fma_rn(DT_Q, a,   zy);
        zx = clip3(zx);                         // ALU-pipe bit-exact clip
        zy = clip3(zy);
    }

    out[i] = make_float2((float)zx, (float)zy);
}

extern "C" void kernel_launch(void* const* d_in, const int* in_sizes, int n_in,
                              void* d_out, int out_size)
{
    const float2* z   = (const float2*)d_in[0];   // (B,2) float32
    float2*       out = (float2*)d_out;           // (B,2) float32

    int n = in_sizes[0] / 2;                      // B particles
    int threads = 256;
    int blocks  = (n + threads - 1) / threads;
    pmflow_kernel<<<blocks, threads>>>(z, out, n);
}

// round 14
// speedup vs baseline: 1.0202x; 1.0202x over previous
#include <cuda_runtime.h>
#include <cuda_bf16.h>

// Constants exactly as the fp32 reference stores them (promoted via float).
// DT_Q = DT/4 and ADV4 = 4*ADVECT are EXACT binary rescalings that cancel the
// 4x-scaled gradient accumulator produced by the doubled-root NR.
#define DT_Q   ((double)0.2f  * 0.25)
#define ADV4   ((double)0.05f * 4.0)
#define EPS_C  ((double)1e-4f)

#define C0 ((double)-2.25f)
#define C1 ((double)-0.75f)
#define C2 ((double) 0.75f)
#define C3 ((double) 2.25f)
// Half-mus: exact binary halving of the promoted fp32 values.
#define MH0 ((double)0.5f * 0.5)
#define MH1 ((double)0.3f * 0.5)
#define MH2 ((double)0.6f * 0.5)
#define MH3 ((double)0.4f * 0.5)

// fp64 rsqrt seed: MUFU.RSQ64H (~2^-21 rel err).
__device__ __forceinline__ double rsq_seed(double x)
{
    double y;
    asm("rsqrt.approx.ftz.f64 %0, %1;" : "=d"(y) : "d"(x));
    return y;
}

// fp64 reciprocal: MUFU.RCP64H seed + 1 Newton -> ~1e-12 rel err.
__device__ __forceinline__ double drcp(double x)
{
    double y;
    asm("rcp.approx.ftz.f64 %0, %1;" : "=d"(y) : "d"(x));
    double t = __fma_rn(-x, y, 2.0);
    return y * t;
}

// One (j,k) interaction, doubled-root NR, r2 fused as fma(dx,dx,ey):
//   yc  = y0*(3 - r2*y0^2)  -> 2/r  (~1e-12)
//   w   = (mu/2)*yc         -> mu/r  (exact)
//   m3p = w*yc^2            -> 4*mu/r^3  (cancelled by DT_Q in epilogue)
// 10 fp64 slots + MUFU — algebraic floor for this interaction.
__device__ __forceinline__ void interact(double ey,
                                         double dx, double dy, double muh,
                                         double& nn, double& gx, double& gy)
{
    double r2  = __fma_rn(dx, dx, ey);
    double y0  = rsq_seed(r2);
    double t   = r2 * y0;
    double c   = __fma_rn(-t, y0, 3.0);
    double yc  = y0 * c;           // 2/r
    double w   = muh * yc;         // mu/r
    nn += w;
    double i2p = yc * yc;          // 4/r^2
    double m3p = w * i2p;          // 4*mu/r^3
    gx = __fma_rn(-m3p, dx, gx);
    gy = __fma_rn(-m3p, dy, gy);
}

__global__ __launch_bounds__(256)
void pmflow_kernel(const float2* __restrict__ z,
                   float2* __restrict__ out,
                   int n)
{
    int i = blockIdx.x * blockDim.x + threadIdx.x;
    if (i >= n) return;

    float2 zp = z[i];
    double zx = (double)zp.x;
    double zy = (double)zp.y;

#pragma unroll
    for (int s = 0; s < 6; s++) {
        // Separable per-axis precompute (scalar, no local arrays).
        double dx0 = zx - C0, dx1 = zx - C1, dx2_ = zx - C2, dx3 = zx - C3;
        double dy0 = zy - C0, dy1 = zy - C1, dy2_ = zy - C2, dy3 = zy - C3;

        double ey0 = __fma_rn(dy0, dy0, EPS_C);
        double ey1 = __fma_rn(dy1, dy1, EPS_C);
        double ey2 = __fma_rn(dy2_, dy2_, EPS_C);
        double ey3 = __fma_rn(dy3, dy3, EPS_C);

        // Single accumulator chains: saves the 3 combine DADDs/step; the
        // 16 interactions still provide abundant independent work between
        // consecutive uses of each accumulator.
        double nn = 1.0, gx = 0.0, gy = 0.0;

        interact(ey0, dx0, dy0, MH0, nn, gx, gy);
        interact(ey0, dx2_, dy0, MH0, nn, gx, gy);
        interact(ey1, dx0, dy1, MH1, nn, gx, gy);
        interact(ey1, dx2_, dy1, MH1, nn, gx, gy);
        interact(ey2, dx0, dy2_, MH2, nn, gx, gy);
        interact(ey2, dx2_, dy2_, MH2, nn, gx, gy);
        interact(ey3, dx0, dy3, MH3, nn, gx, gy);
        interact(ey3, dx2_, dy3, MH3, nn, gx, gy);

        interact(ey0, dx1, dy0, MH0, nn, gx, gy);
        interact(ey0, dx3, dy0, MH0, nn, gx, gy);
        interact(ey1, dx1, dy1, MH1, nn, gx, gy);
        interact(ey1, dx3, dy1, MH1, nn, gx, gy);
        interact(ey2, dx1, dy2_, MH2, nn, gx, gy);
        interact(ey2, dx3, dy2_, MH2, nn, gx, gy);
        interact(ey3, dx1, dy3, MH3, nn, gx, gy);
        interact(ey3, dx3, dy3, MH3, nn, gx, gy);

        double invn = drcp(nn);
        double gxi  = gx * invn;                // 4 * gx/n
        double a    = __fma_rn(gy, invn, ADV4); // 4 * (gy/n + ADVECT)
        zx = __fma_rn(DT_Q, gxi, zx);           // DT/4 cancels the 4 exactly
        zy = __fma_rn(DT_Q, a,   zy);
        zx = fmin(fmax(zx, -3.0), 3.0);
        zy = fmin(fmax(zy, -3.0), 3.0);
    }

    out[i] = make_float2((float)zx, (float)zy);
}

extern "C" void kernel_launch(void* const* d_in, const int* in_sizes, int n_in,
                              void* d_out, int out_size)
{
    const float2* z   = (const float2*)d_in[0];   // (B,2) float32
    float2*       out = (float2*)d_out;           // (B,2) float32

    int n = in_sizes[0] / 2;                      // B particles
    int threads = 256;
    int blocks  = (n + threads - 1) / threads;
    pmflow_kernel<<<blocks, threads>>>(z, out, n);
}